// round 8
// baseline (speedup 1.0000x reference)
#include <cuda_runtime.h>
#include <cuda_bf16.h>
#include <cstdint>

#define T_SEQ 512
#define DIN   32
#define HDIM  64
#define G     256     // 4*H gate rows
#define NB    8       // batches per CTA
#define NBT   4       // batches per thread
#define NTHR  512     // A: warps 0-7 (layer 0), B: warps 8-15 (layer 1)
#define HALF  256
#define SW0_S 68      // Whh0 row stride: 68%32=4 -> conflict-free LDS.128
#define SW1_S 132     // [Wih1|Whh1] row stride: 132%32=4 -> conflict-free
#define ZB_S  8       // gate rows stored as STS.128

// smem floats: sW0 17408 | sW1 33792 | zb0 2048 | zb1 2048 | in0 768
//              h0buf 2*512=1024 | h1buf 512      total 57600 fl = 230400 B
#define SMEM_FLOATS (G*SW0_S + G*SW1_S + 2*(G*ZB_S) + NB*96 + 2*NB*64 + NB*64)

__device__ __forceinline__ unsigned long long pack2(float lo, float hi) {
    unsigned long long r;
    asm("mov.b64 %0, {%1,%2};" : "=l"(r) : "f"(lo), "f"(hi));
    return r;
}
__device__ __forceinline__ void fma2(unsigned long long& d,
                                     unsigned long long a, unsigned long long b) {
    asm("fma.rn.f32x2 %0, %1, %2, %0;" : "+l"(d) : "l"(a), "l"(b));
}
__device__ __forceinline__ float hsum2(unsigned long long v) {
    float lo, hi;
    asm("mov.b64 {%0,%1}, %2;" : "=f"(lo), "=f"(hi) : "l"(v));
    return lo + hi;
}
__device__ __forceinline__ float sigmoid_fast(float x) {
    return __fdividef(1.0f, 1.0f + __expf(-x));
}
__device__ __forceinline__ float tanh_fast(float x) {
    return 1.0f - __fdividef(2.0f, __expf(2.0f * x) + 1.0f);
}
__device__ __forceinline__ void bar_sync(int id, int cnt) {
    asm volatile("bar.sync %0, %1;" :: "r"(id), "r"(cnt) : "memory");
}
__device__ __forceinline__ void bar_arrive(int id, int cnt) {
    asm volatile("bar.arrive %0, %1;" :: "r"(id), "r"(cnt) : "memory");
}

extern __shared__ float smem[];

__global__ void __launch_bounds__(NTHR, 1)
lstm_return_kernel(const float* __restrict__ x,
                   const float* __restrict__ Wih0, const float* __restrict__ Whh0,
                   const float* __restrict__ bih0, const float* __restrict__ bhh0,
                   const float* __restrict__ Wih1, const float* __restrict__ Whh1,
                   const float* __restrict__ bih1, const float* __restrict__ bhh1,
                   const float* __restrict__ W1,   const float* __restrict__ b1,
                   const float* __restrict__ W2,   const float* __restrict__ b2,
                   float* __restrict__ out)
{
    float* sW0   = smem;                  // [256][68]  Whh0
    float* sW1   = sW0 + G * SW0_S;       // [256][132] [Wih1|Whh1]
    float* zb0   = sW1 + G * SW1_S;       // [256][8]   L0 gates
    float* zb1   = zb0 + G * ZB_S;        // [256][8]   L1 gates
    float* in0   = zb1 + G * ZB_S;        // [8][96]    x | h0  (A-private)
    float* h0buf = in0 + NB * 96;         // [2][8][64] A->B hand-off
    float* h1buf = h0buf + 2 * NB * 64;   // [8][64]    B-private h1

    const int tid   = threadIdx.x;
    const bool grpA = (tid < HALF);
    const int jl    = tid & 127;          // rows jl, jl+128 of its layer
    const int bg    = (tid >> 7) & 1;     // batch group: batches bg*4..bg*4+3
    const int bb    = bg * NBT;
    const int bbase = blockIdx.x * NB;

    // ---- stage weights into smem ----
    for (int i = tid; i < G * HDIM; i += NTHR) {
        int r = i >> 6, c = i & 63;
        sW0[r * SW0_S + c]        = Whh0[i];
        sW1[r * SW1_S + c]        = Wih1[i];
        sW1[r * SW1_S + HDIM + c] = Whh1[i];
    }
    for (int i = tid; i < NB * 96; i += NTHR) in0[i] = 0.0f;
    for (int i = tid; i < 3 * NB * 64; i += NTHR) h0buf[i] = 0.0f; // h0buf+h1buf

    // ---- A: Wih0 rows jl, jl+128 in registers ----
    unsigned long long wx0[16], wx1[16];
#pragma unroll
    for (int k = 0; k < 16; k++) {
        int r0 = jl * DIN + 2 * k, r1 = (jl + 128) * DIN + 2 * k;
        wx0[k] = grpA ? pack2(Wih0[r0], Wih0[r0 + 1]) : 0ull;
        wx1[k] = grpA ? pack2(Wih0[r1], Wih0[r1 + 1]) : 0ull;
    }
    float bsA, bsB;
    if (grpA) { bsA = bih0[jl] + bhh0[jl]; bsB = bih0[jl + 128] + bhh0[jl + 128]; }
    else      { bsA = bih1[jl] + bhh1[jl]; bsB = bih1[jl + 128] + bhh1[jl + 128]; }
    const bool row2_tanh = (jl < 64);     // second row is g-gate iff jl<64

    // cell ownership: 2 cells/thread: unit cu, batches 2*cp, 2*cp+1
    const int cu = tid & 63;
    const int cp = ((jl >> 6) << 1) | bg; // 0..3
    float cst[2] = {0.f, 0.f};

    // x staging (A, 256 threads): thread -> (batch xb, channel xk)
    const int xb = (tid >> 5) & 7, xk = tid & 31;
    const float* xptr = x + ((size_t)(bbase + xb) * T_SEQ) * DIN + xk;
    float xcur = 0.f;

    const float* w0rA = sW0 + jl * SW0_S;
    const float* w0rB = sW0 + (jl + 128) * SW0_S;
    const float* w1rA = sW1 + jl * SW1_S;
    const float* w1rB = sW1 + (jl + 128) * SW1_S;

    if (grpA) {
        in0[xb * 96 + xk] = xptr[0];      // stage x(0)
        xcur = xptr[DIN];                  // prefetch x(1)
    }
    __syncthreads();

    if (grpA) {
        // ============================ GROUP A: layer 0 ============================
        for (int t = 0; t < T_SEQ; t++) {
            const int p = t & 1;
            unsigned long long a0[NBT], a1[NBT];
#pragma unroll
            for (int b = 0; b < NBT; b++) { a0[b] = pack2(bsA, 0.f); a1[b] = pack2(bsB, 0.f); }
#pragma unroll
            for (int kc = 0; kc < 8; kc++) {
                const unsigned long long u0 = wx0[2*kc], u1 = wx0[2*kc+1];
                const unsigned long long v0 = wx1[2*kc], v1 = wx1[2*kc+1];
#pragma unroll
                for (int b = 0; b < NBT; b++) {
                    ulonglong2 iv = *(const ulonglong2*)(in0 + (bb + b) * 96 + 4 * kc);
                    fma2(a0[b], u0, iv.x); fma2(a0[b], u1, iv.y);
                    fma2(a1[b], v0, iv.x); fma2(a1[b], v1, iv.y);
                }
            }
#pragma unroll
            for (int kc = 0; kc < 16; kc++) {
                ulonglong2 wvA = *(const ulonglong2*)(w0rA + 4 * kc);
                ulonglong2 wvB = *(const ulonglong2*)(w0rB + 4 * kc);
#pragma unroll
                for (int b = 0; b < NBT; b++) {
                    ulonglong2 iv = *(const ulonglong2*)(in0 + (bb + b) * 96 + 32 + 4 * kc);
                    fma2(a0[b], wvA.x, iv.x); fma2(a0[b], wvA.y, iv.y);
                    fma2(a1[b], wvB.x, iv.x); fma2(a1[b], wvB.y, iv.y);
                }
            }
            float r0[NBT], r1[NBT];
#pragma unroll
            for (int b = 0; b < NBT; b++) {
                r0[b] = sigmoid_fast(hsum2(a0[b]));
                float z1 = hsum2(a1[b]);
                r1[b] = row2_tanh ? tanh_fast(z1) : sigmoid_fast(z1);
            }
            *(float4*)(zb0 + jl * ZB_S + bb)         = make_float4(r0[0], r0[1], r0[2], r0[3]);
            *(float4*)(zb0 + (jl + 128) * ZB_S + bb) = make_float4(r1[0], r1[1], r1[2], r1[3]);

            bar_sync(5, HALF);                       // zb0 visible within A
            if (t >= 2) bar_sync(3 + p, NTHR);       // h0buf[p] free (B consumed t-2)

            // ---- cell0(t): 2 cells per thread ----
            {
                const float* zc = zb0 + cu * ZB_S;
                float* hb = h0buf + p * (NB * 64);
#pragma unroll
                for (int q = 0; q < 2; q++) {
                    int b = 2 * cp + q;
                    float i_ = zc[0 * 64 * ZB_S + b];
                    float f_ = zc[1 * 64 * ZB_S + b];
                    float g_ = zc[2 * 64 * ZB_S + b];
                    float o_ = zc[3 * 64 * ZB_S + b];
                    cst[q] = f_ * cst[q] + i_ * g_;
                    float h = o_ * tanh_fast(cst[q]);
                    in0[b * 96 + 32 + cu] = h;       // for gates0(t+1)
                    hb[b * 64 + cu]       = h;       // for B's gates1(t)
                }
            }
            // stage x(t+1), prefetch x(t+2)
            if (t + 1 < T_SEQ) {
                in0[xb * 96 + xk] = xcur;
                if (t + 2 < T_SEQ) xcur = xptr[(size_t)(t + 2) * DIN];
            }
            bar_arrive(1 + p, NTHR);                 // h0(t) ready for B
            bar_sync(6, HALF);                       // in0 writes visible within A
        }
    } else {
        // ============================ GROUP B: layer 1 ============================
        for (int t = 0; t < T_SEQ; t++) {
            const int p = t & 1;
            bar_sync(1 + p, NTHR);                   // wait h0(t); fences h1buf too
            const float* h0p = h0buf + p * (NB * 64);

            unsigned long long a0[NBT], a1[NBT];
#pragma unroll
            for (int b = 0; b < NBT; b++) { a0[b] = pack2(bsA, 0.f); a1[b] = pack2(bsB, 0.f); }
#pragma unroll
            for (int kc = 0; kc < 16; kc++) {        // h0 part (Wih1)
                ulonglong2 wvA = *(const ulonglong2*)(w1rA + 4 * kc);
                ulonglong2 wvB = *(const ulonglong2*)(w1rB + 4 * kc);
#pragma unroll
                for (int b = 0; b < NBT; b++) {
                    ulonglong2 iv = *(const ulonglong2*)(h0p + (bb + b) * 64 + 4 * kc);
                    fma2(a0[b], wvA.x, iv.x); fma2(a0[b], wvA.y, iv.y);
                    fma2(a1[b], wvB.x, iv.x); fma2(a1[b], wvB.y, iv.y);
                }
            }
            bar_arrive(3 + p, NTHR);                 // h0buf[p] consumed
#pragma unroll
            for (int kc = 0; kc < 16; kc++) {        // h1 part (Whh1)
                ulonglong2 wvA = *(const ulonglong2*)(w1rA + 64 + 4 * kc);
                ulonglong2 wvB = *(const ulonglong2*)(w1rB + 64 + 4 * kc);
#pragma unroll
                for (int b = 0; b < NBT; b++) {
                    ulonglong2 iv = *(const ulonglong2*)(h1buf + (bb + b) * 64 + 4 * kc);
                    fma2(a0[b], wvA.x, iv.x); fma2(a0[b], wvA.y, iv.y);
                    fma2(a1[b], wvB.x, iv.x); fma2(a1[b], wvB.y, iv.y);
                }
            }
            float r0[NBT], r1[NBT];
#pragma unroll
            for (int b = 0; b < NBT; b++) {
                r0[b] = sigmoid_fast(hsum2(a0[b]));
                float z1 = hsum2(a1[b]);
                r1[b] = row2_tanh ? tanh_fast(z1) : sigmoid_fast(z1);
            }
            *(float4*)(zb1 + jl * ZB_S + bb)         = make_float4(r0[0], r0[1], r0[2], r0[3]);
            *(float4*)(zb1 + (jl + 128) * ZB_S + bb) = make_float4(r1[0], r1[1], r1[2], r1[3]);

            bar_sync(7, HALF);                       // zb1 visible within B
            // ---- cell1(t): 2 cells per thread ----
            {
                const float* zc = zb1 + cu * ZB_S;
#pragma unroll
                for (int q = 0; q < 2; q++) {
                    int b = 2 * cp + q;
                    float i_ = zc[0 * 64 * ZB_S + b];
                    float f_ = zc[1 * 64 * ZB_S + b];
                    float g_ = zc[2 * 64 * ZB_S + b];
                    float o_ = zc[3 * 64 * ZB_S + b];
                    cst[q] = f_ * cst[q] + i_ * g_;
                    h1buf[b * 64 + cu] = o_ * tanh_fast(cst[q]);
                }
            }
            // h1buf write->read for t+1 ordered by bar.sync(1+p') rendezvous
        }
    }

    __syncthreads();   // final h1 visible to all

    // ===== head: out = relu(h1 @ W1^T + b1) @ W2^T + b2 =====
    if (tid < 256) {
        const int hb = tid >> 5;
        const int hu = tid & 31;
        const float* w1r = W1 + hu * HDIM;
        const float* hv  = h1buf + hb * 64;
        float acc = b1[hu];
#pragma unroll
        for (int k = 0; k < HDIM; k++) acc += w1r[k] * hv[k];
        acc = fmaxf(acc, 0.0f) * W2[hu];
        zb0[hb * 32 + hu] = acc;
    }
    __syncthreads();
    if (tid < NB) {
        float s = b2[0];
#pragma unroll
        for (int u = 0; u < 32; u++) s += zb0[tid * 32 + u];
        out[bbase + tid] = s;
    }
}

extern "C" void kernel_launch(void* const* d_in, const int* in_sizes, int n_in,
                              void* d_out, int out_size) {
    (void)in_sizes; (void)n_in; (void)out_size;
    const float* x    = (const float*)d_in[0];
    const float* Wih0 = (const float*)d_in[1];
    const float* Whh0 = (const float*)d_in[2];
    const float* bih0 = (const float*)d_in[3];
    const float* bhh0 = (const float*)d_in[4];
    const float* Wih1 = (const float*)d_in[5];
    const float* Whh1 = (const float*)d_in[6];
    const float* bih1 = (const float*)d_in[7];
    const float* bhh1 = (const float*)d_in[8];
    const float* W1   = (const float*)d_in[9];
    const float* b1   = (const float*)d_in[10];
    const float* W2   = (const float*)d_in[11];
    const float* b2   = (const float*)d_in[12];
    float* out = (float*)d_out;

    const size_t smem_bytes = (size_t)SMEM_FLOATS * sizeof(float);
    cudaFuncSetAttribute(lstm_return_kernel,
                         cudaFuncAttributeMaxDynamicSharedMemorySize,
                         (int)smem_bytes);
    lstm_return_kernel<<<1024 / NB, NTHR, smem_bytes>>>(
        x, Wih0, Whh0, bih0, bhh0, Wih1, Whh1, bih1, bhh1,
        W1, b1, W2, b2, out);
}

// round 9
// speedup vs baseline: 1.0978x; 1.0978x over previous
#include <cuda_runtime.h>
#include <cuda_bf16.h>
#include <cstdint>

#define T_SEQ 512
#define BATCH 1024
#define DIN   32
#define HDIM  64
#define G     256     // 4*H gate rows
#define NB    8       // batches per CTA
#define NTHR  256     // A: warps 0-3 (layer 0), B: warps 4-7 (layer 1)
#define SW0_S 68      // Whh0 row stride: 68%32=4 -> 2-wf LDS.128 at 16 distinct rows
#define SW1_S 132     // [Wih1|Whh1] row stride: 132%32=4 -> same

// Precomputed x-path: XW[t][b][j] = bih0[j]+bhh0[j] + x[b][t]@Wih0[j]   (512 MB)
__device__ float g_xw[(size_t)T_SEQ * BATCH * G];

// smem floats: sW0 17408 | sW1 33792 | h0T 2*512 | h1T 512  = 52736 fl = 210944 B
#define SMEM_FLOATS (G*SW0_S + G*SW1_S + 2*(NB*64) + NB*64)

__device__ __forceinline__ unsigned long long pack2(float lo, float hi) {
    unsigned long long r;
    asm("mov.b64 %0, {%1,%2};" : "=l"(r) : "f"(lo), "f"(hi));
    return r;
}
__device__ __forceinline__ void fma2(unsigned long long& d,
                                     unsigned long long a, unsigned long long b) {
    asm("fma.rn.f32x2 %0, %1, %2, %0;" : "+l"(d) : "l"(a), "l"(b));
}
__device__ __forceinline__ float hsum2(unsigned long long v) {
    float lo, hi;
    asm("mov.b64 {%0,%1}, %2;" : "=f"(lo), "=f"(hi) : "l"(v));
    return lo + hi;
}
__device__ __forceinline__ float sigmoid_fast(float x) {
    return __fdividef(1.0f, 1.0f + __expf(-x));
}
__device__ __forceinline__ float tanh_fast(float x) {
    return 1.0f - __fdividef(2.0f, __expf(2.0f * x) + 1.0f);
}
__device__ __forceinline__ void bar_sync(int id, int cnt) {
    asm volatile("bar.sync %0, %1;" :: "r"(id), "r"(cnt) : "memory");
}
__device__ __forceinline__ void bar_arrive(int id, int cnt) {
    asm volatile("bar.arrive %0, %1;" :: "r"(id), "r"(cnt) : "memory");
}

// ===================== pre-kernel: XW = x @ Wih0^T + bias0 =====================
// grid = (BATCH * 8) blocks of 256 threads; block = (batch b, 64-step t-tile)
__global__ void __launch_bounds__(256, 4)
xw_kernel(const float* __restrict__ x,
          const float* __restrict__ Wih0,
          const float* __restrict__ bih0,
          const float* __restrict__ bhh0)
{
    __shared__ float xs[64 * DIN];    // 8 KB x tile
    const int b  = blockIdx.x >> 3;
    const int t0 = (blockIdx.x & 7) * 64;
    const int j  = threadIdx.x;

    unsigned long long wp[16];
#pragma unroll
    for (int k = 0; k < 16; k++)
        wp[k] = pack2(Wih0[j * DIN + 2 * k], Wih0[j * DIN + 2 * k + 1]);
    const float bias = bih0[j] + bhh0[j];

    for (int i = j; i < 64 * DIN; i += 256)
        xs[i] = x[((size_t)b * T_SEQ + t0) * DIN + i];
    __syncthreads();

    for (int tt = 0; tt < 64; tt++) {
        unsigned long long acc = pack2(bias, 0.0f);
#pragma unroll
        for (int kc = 0; kc < 8; kc++) {
            ulonglong2 iv = *(const ulonglong2*)(xs + tt * DIN + 4 * kc);
            fma2(acc, wp[2 * kc],     iv.x);
            fma2(acc, wp[2 * kc + 1], iv.y);
        }
        g_xw[((size_t)(t0 + tt) * BATCH + b) * G + j] = hsum2(acc);
    }
}

// ===================== main persistent LSTM kernel =====================
extern __shared__ float smem[];

__global__ void __launch_bounds__(NTHR, 1)
lstm_return_kernel(const float* __restrict__ x,
                   const float* __restrict__ Wih0, const float* __restrict__ Whh0,
                   const float* __restrict__ bih0, const float* __restrict__ bhh0,
                   const float* __restrict__ Wih1, const float* __restrict__ Whh1,
                   const float* __restrict__ bih1, const float* __restrict__ bhh1,
                   const float* __restrict__ W1,   const float* __restrict__ b1,
                   const float* __restrict__ W2,   const float* __restrict__ b2,
                   float* __restrict__ out)
{
    float* sW0 = smem;                 // [256][68]  Whh0
    float* sW1 = sW0 + G * SW0_S;      // [256][132] [Wih1|Whh1]
    float* h0T = sW1 + G * SW1_S;      // [2][16][8][4]  h0, transposed, dbl-buf
    float* h1T = h0T + 2 * 512;        // [16][8][4]     h1, transposed

    const int tid   = threadIdx.x;
    const int l     = tid & 31;
    const bool grpA = (tid < 128);
    const int gw    = (tid >> 5) & 3;       // warp index within group
    const int rq    = gw * 16 + (l & 15);   // owned unit (rows rq+64m, m=0..3)
    const int bg    = l >> 4;               // batch half
    const int bbase = blockIdx.x * NB;

    // ---- stage weights ----
    for (int i = tid; i < G * HDIM; i += NTHR) {
        int r = i >> 6, c = i & 63;
        sW0[r * SW0_S + c]        = Whh0[i];
        sW1[r * SW1_S + c]        = Wih1[i];
        sW1[r * SW1_S + HDIM + c] = Whh1[i];
    }
    for (int i = tid; i < 3 * 512; i += NTHR) h0T[i] = 0.0f;   // h0T + h1T

    // biases for B rows (A bias folded into XW)
    float bs1[4];
#pragma unroll
    for (int m = 0; m < 4; m++)
        bs1[m] = grpA ? 0.0f : (bih1[rq + 64 * m] + bhh1[rq + 64 * m]);

    float cst[4] = {0.f, 0.f, 0.f, 0.f};    // cell states, 4 batches

    // XW prefetch pointers (A only): per q, base for (batch bbase+bg*4+q, row rq)
    const size_t tstep = (size_t)BATCH * G;
    const float* xwb = g_xw + (size_t)(bbase + bg * 4) * G + rq;
    float xwp[16];
    if (grpA) {
#pragma unroll
        for (int q = 0; q < 4; q++)
#pragma unroll
            for (int m = 0; m < 4; m++)
                xwp[m * 4 + q] = xwb[(size_t)q * G + 64 * m];   // t = 0
    }

    const int wr0 = rq * SW0_S, wr1 = rq * SW1_S;

    __syncthreads();

    if (grpA) {
        // =========================== GROUP A: layer 0 ===========================
        for (int t = 0; t < T_SEQ; t++) {
            const int p = t & 1;
            unsigned long long acc[16];
#pragma unroll
            for (int i = 0; i < 16; i++) acc[i] = pack2(xwp[i], 0.0f);
            // prefetch XW for t+1
            if (t + 1 < T_SEQ) {
                const float* xn = xwb + (size_t)(t + 1) * tstep;
#pragma unroll
                for (int q = 0; q < 4; q++)
#pragma unroll
                    for (int m = 0; m < 4; m++)
                        xwp[m * 4 + q] = xn[(size_t)q * G + 64 * m];
            }
            // gates: h0(t-1) from h0T[p^1]
            const float* h0p = h0T + (p ^ 1) * 512;
#pragma unroll
            for (int kc = 0; kc < 16; kc++) {
                ulonglong2 wv0 = *(const ulonglong2*)(sW0 + wr0 +   0 * SW0_S + 4 * kc);
                ulonglong2 wv1 = *(const ulonglong2*)(sW0 + wr0 +  64 * SW0_S + 4 * kc);
                ulonglong2 wv2 = *(const ulonglong2*)(sW0 + wr0 + 128 * SW0_S + 4 * kc);
                ulonglong2 wv3 = *(const ulonglong2*)(sW0 + wr0 + 192 * SW0_S + 4 * kc);
#pragma unroll
                for (int q = 0; q < 4; q++) {
                    ulonglong2 iv = *(const ulonglong2*)(h0p + kc * 32 + (bg * 4 + q) * 4);
                    fma2(acc[0 * 4 + q], wv0.x, iv.x); fma2(acc[0 * 4 + q], wv0.y, iv.y);
                    fma2(acc[1 * 4 + q], wv1.x, iv.x); fma2(acc[1 * 4 + q], wv1.y, iv.y);
                    fma2(acc[2 * 4 + q], wv2.x, iv.x); fma2(acc[2 * 4 + q], wv2.y, iv.y);
                    fma2(acc[3 * 4 + q], wv3.x, iv.x); fma2(acc[3 * 4 + q], wv3.y, iv.y);
                }
            }
            if (t >= 2) bar_sync(3 + p, NTHR);   // h0T[p] free (B consumed t-2)
            // activations + cell + h writes
            float* h0c = h0T + p * 512;
#pragma unroll
            for (int q = 0; q < 4; q++) {
                float zi = hsum2(acc[0 * 4 + q]);
                float zf = hsum2(acc[1 * 4 + q]);
                float zg = hsum2(acc[2 * 4 + q]);
                float zo = hsum2(acc[3 * 4 + q]);
                float i_ = sigmoid_fast(zi);
                float f_ = sigmoid_fast(zf);
                float g_ = tanh_fast(zg);
                float o_ = sigmoid_fast(zo);
                cst[q] = f_ * cst[q] + i_ * g_;
                float h = o_ * tanh_fast(cst[q]);
                h0c[(rq >> 2) * 32 + (bg * 4 + q) * 4 + (rq & 3)] = h;
            }
            bar_arrive(1 + p, NTHR);             // h0(t) ready for B
            bar_sync(5, 128);                    // A-internal: h0T[p] visible to A
        }
    } else {
        // =========================== GROUP B: layer 1 ===========================
        for (int t = 0; t < T_SEQ; t++) {
            const int p = t & 1;
            bar_sync(1 + p, NTHR);               // wait h0(t); orders h1T too
            const float* h0p = h0T + p * 512;

            unsigned long long acc[16];
#pragma unroll
            for (int m = 0; m < 4; m++)
#pragma unroll
                for (int q = 0; q < 4; q++) acc[m * 4 + q] = pack2(bs1[m], 0.0f);
            // part 1: h0 @ Wih1^T
#pragma unroll
            for (int kc = 0; kc < 16; kc++) {
                ulonglong2 wv0 = *(const ulonglong2*)(sW1 + wr1 +   0 * SW1_S + 4 * kc);
                ulonglong2 wv1 = *(const ulonglong2*)(sW1 + wr1 +  64 * SW1_S + 4 * kc);
                ulonglong2 wv2 = *(const ulonglong2*)(sW1 + wr1 + 128 * SW1_S + 4 * kc);
                ulonglong2 wv3 = *(const ulonglong2*)(sW1 + wr1 + 192 * SW1_S + 4 * kc);
#pragma unroll
                for (int q = 0; q < 4; q++) {
                    ulonglong2 iv = *(const ulonglong2*)(h0p + kc * 32 + (bg * 4 + q) * 4);
                    fma2(acc[0 * 4 + q], wv0.x, iv.x); fma2(acc[0 * 4 + q], wv0.y, iv.y);
                    fma2(acc[1 * 4 + q], wv1.x, iv.x); fma2(acc[1 * 4 + q], wv1.y, iv.y);
                    fma2(acc[2 * 4 + q], wv2.x, iv.x); fma2(acc[2 * 4 + q], wv2.y, iv.y);
                    fma2(acc[3 * 4 + q], wv3.x, iv.x); fma2(acc[3 * 4 + q], wv3.y, iv.y);
                }
            }
            bar_arrive(3 + p, NTHR);             // h0T[p] consumed
            // part 2: h1 @ Whh1^T
#pragma unroll
            for (int kc = 0; kc < 16; kc++) {
                ulonglong2 wv0 = *(const ulonglong2*)(sW1 + wr1 +   0 * SW1_S + 64 + 4 * kc);
                ulonglong2 wv1 = *(const ulonglong2*)(sW1 + wr1 +  64 * SW1_S + 64 + 4 * kc);
                ulonglong2 wv2 = *(const ulonglong2*)(sW1 + wr1 + 128 * SW1_S + 64 + 4 * kc);
                ulonglong2 wv3 = *(const ulonglong2*)(sW1 + wr1 + 192 * SW1_S + 64 + 4 * kc);
#pragma unroll
                for (int q = 0; q < 4; q++) {
                    ulonglong2 iv = *(const ulonglong2*)(h1T + kc * 32 + (bg * 4 + q) * 4);
                    fma2(acc[0 * 4 + q], wv0.x, iv.x); fma2(acc[0 * 4 + q], wv0.y, iv.y);
                    fma2(acc[1 * 4 + q], wv1.x, iv.x); fma2(acc[1 * 4 + q], wv1.y, iv.y);
                    fma2(acc[2 * 4 + q], wv2.x, iv.x); fma2(acc[2 * 4 + q], wv2.y, iv.y);
                    fma2(acc[3 * 4 + q], wv3.x, iv.x); fma2(acc[3 * 4 + q], wv3.y, iv.y);
                }
            }
#pragma unroll
            for (int q = 0; q < 4; q++) {
                float zi = hsum2(acc[0 * 4 + q]);
                float zf = hsum2(acc[1 * 4 + q]);
                float zg = hsum2(acc[2 * 4 + q]);
                float zo = hsum2(acc[3 * 4 + q]);
                float i_ = sigmoid_fast(zi);
                float f_ = sigmoid_fast(zf);
                float g_ = tanh_fast(zg);
                float o_ = sigmoid_fast(zo);
                cst[q] = f_ * cst[q] + i_ * g_;
                h1T[(rq >> 2) * 32 + (bg * 4 + q) * 4 + (rq & 3)] = o_ * tanh_fast(cst[q]);
            }
            // h1T write->read for t+1 ordered by bar_sync(1+p') full-CTA rendezvous
        }
    }

    __syncthreads();   // final h1 visible to all

    // ===== head: out = relu(h1 @ W1^T + b1) @ W2^T + b2 =====
    {
        const int hb = tid >> 5;    // batch 0..7
        const int hu = tid & 31;    // hidden unit 0..31
        const float* w1r = W1 + hu * HDIM;
        float acc = b1[hu];
#pragma unroll
        for (int k = 0; k < HDIM; k++)
            acc += w1r[k] * h1T[(k >> 2) * 32 + hb * 4 + (k & 3)];
        acc = fmaxf(acc, 0.0f) * W2[hu];
        sW0[hb * 32 + hu] = acc;    // reuse sW0 as scratch
    }
    __syncthreads();
    if (tid < NB) {
        float s = b2[0];
#pragma unroll
        for (int u = 0; u < 32; u++) s += sW0[tid * 32 + u];
        out[bbase + tid] = s;
    }
}

extern "C" void kernel_launch(void* const* d_in, const int* in_sizes, int n_in,
                              void* d_out, int out_size) {
    (void)in_sizes; (void)n_in; (void)out_size;
    const float* x    = (const float*)d_in[0];
    const float* Wih0 = (const float*)d_in[1];
    const float* Whh0 = (const float*)d_in[2];
    const float* bih0 = (const float*)d_in[3];
    const float* bhh0 = (const float*)d_in[4];
    const float* Wih1 = (const float*)d_in[5];
    const float* Whh1 = (const float*)d_in[6];
    const float* bih1 = (const float*)d_in[7];
    const float* bhh1 = (const float*)d_in[8];
    const float* W1   = (const float*)d_in[9];
    const float* b1   = (const float*)d_in[10];
    const float* W2   = (const float*)d_in[11];
    const float* b2   = (const float*)d_in[12];
    float* out = (float*)d_out;

    // pre-pass: x-path GEMM off the serial path
    xw_kernel<<<BATCH * 8, 256>>>(x, Wih0, bih0, bhh0);

    const size_t smem_bytes = (size_t)SMEM_FLOATS * sizeof(float);
    cudaFuncSetAttribute(lstm_return_kernel,
                         cudaFuncAttributeMaxDynamicSharedMemorySize,
                         (int)smem_bytes);
    lstm_return_kernel<<<BATCH / NB, NTHR, smem_bytes>>>(
        x, Wih0, Whh0, bih0, bhh0, Wih1, Whh1, bih1, bhh1,
        W1, b1, W2, b2, out);
}